// round 13
// baseline (speedup 1.0000x reference)
#include <cuda_runtime.h>
#include <math.h>

// Problem constants
#define NBc   16
#define NAc   5
#define NKc   9
#define NCc   13
#define NHc   38
#define NWc   38
#define MAXTc 50
#define NPIX  (NHc*NWc)        // 1444
#define NANCH (NAc*NPIX)       // 7220
#define NTOTc (NBc*NANCH)      // 115520
#define CHPA  (2*NKc+1+NCc)    // 32
#define TROW  21

#define NPAIR (NANCH/2)        // 3610 cell-pairs per batch
#define TPB   256
#define BPB   ((NPAIR + TPB - 1)/TPB)  // 15 blocks per batch
#define NBLK  (NBc*BPB)                // 240 blocks

#define SCX   (640.0f/38.0f)
#define SCY   (480.0f/38.0f)
#define DENOM9   57.50150489f
#define STHRESH  34.50090293f   // 0.6 * 9 * (e^2 - 1)
// ssum > STHRESH requires max corner term >= STHRESH/9 -> some d2 < 288.12
#define GATE2    290.0f

__device__ float g_part[NBLK][2];
__device__ int   g_cnt = 0;

__device__ __forceinline__ float sigf(float x) { return 1.0f / (1.0f + __expf(-x)); }

__global__ void __launch_bounds__(TPB, 3)
k_main(const float* __restrict__ out,
       const float* __restrict__ tgt,
       const float* __restrict__ anc,
       const void*  __restrict__ epoch_ptr,
       float* __restrict__ d_out) {
    __shared__ float  s_t[MAXTc*TROW];                // staged target rows
    __shared__ int    s_nv;
    __shared__ int    s_key[MAXTc];
    __shared__ float  s_cls[MAXTc];
    __shared__ __align__(16) float4 s_gq[MAXTc][5];   // corners (10 f2 slots)
    __shared__ __align__(16) float2 s_v[MAXTc*NKc];   // coord targets
    __shared__ float2 s_wred[TPB/32];
    __shared__ bool   s_last;

    const int tid  = threadIdx.x;
    const int lane = tid & 31;
    const int wid  = tid >> 5;
    const int b    = blockIdx.x / BPB;
    const int pp   = (blockIdx.x % BPB) * TPB + tid;   // pair index
    const bool ok  = (pp < NPAIR);
    const float* tgb = tgt + (size_t)b * (MAXTc*TROW);

    // ---- per-pair channel loads: LDG.64 per channel serves cells w, w+1 ----
    int a = 0, h = 0, w = 0;
    const float* baseo = out;
    float Px[2][NKc], Py[2][NKc], confv[2] = {0.0f, 0.0f};
    if (ok) {
        a = pp / (NPIX/2);
        int prem = pp % (NPIX/2);
        int pix = prem * 2;                 // even; pair never crosses a row
        h = pix / NWc; w = pix % NWc;       // w <= 36, so w+1 valid
        baseo = out + ((size_t)(b * NAc + a) * CHPA) * NPIX + pix;
        #pragma unroll
        for (int k = 0; k < NKc; ++k) {
            float2 xv = *(const float2*)(baseo + (2*k)   * NPIX);
            float2 yv = *(const float2*)(baseo + (2*k+1) * NPIX);
            if (k == 0) {
                xv.x = sigf(xv.x); xv.y = sigf(xv.y);
                yv.x = sigf(yv.x); yv.y = sigf(yv.y);
            }
            Px[0][k] = (xv.x + (float)w)        * SCX;
            Px[1][k] = (xv.y + (float)(w + 1))  * SCX;
            Py[0][k] = (yv.x + (float)h) * SCY;
            Py[1][k] = (yv.y + (float)h) * SCY;
        }
        float2 rc = *(const float2*)(baseo + (2*NKc) * NPIX);
        confv[0] = sigf(rc.x);
        confv[1] = sigf(rc.y);
    }

    // ---- stage targets coalesced -------------------------------------------
    for (int i = tid; i < MAXTc*TROW; i += TPB)
        s_t[i] = tgb[i];
    __syncthreads();

    // ---- validity prefix via ballots (warp 0, conflict-free LDS) -----------
    if (wid == 0) {
        unsigned m0 = __ballot_sync(0xFFFFFFFFu, s_t[lane*TROW + 1] != 0.0f);
        unsigned m1 = __ballot_sync(0xFFFFFFFFu,
                          (lane < MAXTc - 32) && (s_t[(lane+32)*TROW + 1] != 0.0f));
        if (lane == 0) {
            int nv;
            if (~m0) nv = __ffs(~m0) - 1;
            else {
                unsigned inv = (~m1) & ((1u << (MAXTc - 32)) - 1u);
                nv = inv ? 32 + __ffs(inv) - 1 : MAXTc;
            }
            s_nv = nv;
        }
    }

    // ---- per-target meta (no tconf; cheap) ----------------------------------
    if (tid < MAXTc && s_t[tid*TROW + 1] != 0.0f) {
        const int t = tid;
        const float* tb = &s_t[t*TROW];

        float gw = tb[19] * (float)NWc;
        float gh = tb[20] * (float)NHc;
        float best = -1.0f; int bn = 0;
        #pragma unroll
        for (int aa = 0; aa < NAc; ++aa) {
            float aw = anc[2*aa], ah = anc[2*aa+1];
            float cw = fminf(gw, aw), ch = fminf(gh, ah);
            float iou = 0.0f;
            if (cw > 0.0f && ch > 0.0f) {
                float ca = cw * ch;
                iou = ca / (gw * gh + aw * ah - ca);
            }
            if (iou > best) { best = iou; bn = aa; }
        }
        int gi0 = (int)floorf(tb[1] * (float)NWc);
        int gj0 = (int)floorf(tb[2] * (float)NHc);
        s_key[t] = (bn << 12) | (gj0 << 6) | gi0;
        s_cls[t] = tb[0];

        float* gq = (float*)&s_gq[t][0];
        #pragma unroll
        for (int k = 0; k < NKc; ++k) {
            float gx = tb[1 + 2*k], gy = tb[2 + 2*k];
            gq[2*k]   = gx * 640.0f;
            gq[2*k+1] = gy * 480.0f;
            s_v[t*NKc + k] = make_float2(gx * (float)NWc - (float)gi0,
                                         gy * (float)NHc - (float)gj0);
        }
        gq[18] = 1.0e9f;  gq[19] = 1.0e9f;   // sentinel 10th corner slot
    }
    __syncthreads();
    const int nv = s_nv;

    // ---- per-pair loss ------------------------------------------------------
    float baseLoss = 0.0f, confLoss = 0.0f;

    if (ok) {
        const int keyA = (a << 12) | (h << 6) | w;
        const int keyB = keyA + 1;          // w+1, same (a, h)
        int mm[2] = {-1, -1};
        for (int t = 0; t < nv; ++t) {
            int kk = s_key[t];
            if (kk == keyA) mm[0] = t;
            if (kk == keyB) mm[1] = t;
        }

        // silence scan: one LDS set per target serves both cells
        int sil[2] = {0, 0};
        for (int t = 0; t < nv; ++t) {
            float4 q0 = s_gq[t][0];
            float4 q1 = s_gq[t][1];
            float4 q2 = s_gq[t][2];
            float4 q3 = s_gq[t][3];
            float4 q4 = s_gq[t][4];
            const float gx[NKc] = {q0.x,q0.z,q1.x,q1.z,q2.x,q2.z,q3.x,q3.z,q4.x};
            const float gy[NKc] = {q0.y,q0.w,q1.y,q1.w,q2.y,q2.w,q3.y,q3.w,q4.y};
            #pragma unroll
            for (int j = 0; j < 2; ++j) {
                float d2[NKc];
                #pragma unroll
                for (int k = 0; k < NKc; ++k) {
                    float dx = Px[j][k] - gx[k];
                    float dy = Py[j][k] - gy[k];
                    d2[k] = fmaf(dx, dx, dy * dy);
                }
                float m01 = fminf(d2[0], d2[1]), m23 = fminf(d2[2], d2[3]);
                float m45 = fminf(d2[4], d2[5]), m67 = fminf(d2[6], d2[7]);
                float dmin = fminf(fminf(fminf(m01, m23), fminf(m45, m67)), d2[8]);
                if (dmin < GATE2) {          // rare
                    float ssum = 0.0f;
                    #pragma unroll
                    for (int k = 0; k < NKc; ++k)
                        if (d2[k] < 6400.0f)
                            ssum += __expf(2.0f - sqrtf(d2[k]) * 0.025f) - 1.0f;
                    if (ssum > STHRESH) sil[j] = 1;
                }
            }
        }

        // per-cell loss terms
        #pragma unroll
        for (int j = 0; j < 2; ++j) {
            const int m = mm[j];
            if (m >= 0) {
                // matched (rare): coord + CE + obj-conf (tconf computed here)
                const float* bj = baseo + j;
                #pragma unroll
                for (int k = 0; k < NKc; ++k) {
                    float xv = bj[(2*k)   * NPIX];
                    float yv = bj[(2*k+1) * NPIX];
                    if (k == 0) { xv = sigf(xv); yv = sigf(yv); }
                    float2 v = s_v[m*NKc + k];
                    float dx = xv - v.x;
                    float dy = yv - v.y;
                    baseLoss += 0.5f * (dx*dx + dy*dy);
                }
                float mx = -1e30f;
                #pragma unroll
                for (int c = 0; c < NCc; ++c)
                    mx = fmaxf(mx, bj[(2*NKc + 1 + c) * NPIX]);
                float se = 0.0f;
                #pragma unroll
                for (int c = 0; c < NCc; ++c)
                    se += __expf(bj[(2*NKc + 1 + c) * NPIX] - mx);
                int lab = (int)s_cls[m];
                lab = lab < 0 ? 0 : (lab > NCc - 1 ? NCc - 1 : lab);
                baseLoss += __logf(se) + mx - bj[(2*NKc + 1 + lab) * NPIX];

                // tconf at the pidx-shifted cell for this target
                int key = s_key[m];
                int gi0 = key & 63, gj0 = (key >> 6) & 63;
                long long p = (long long)b * NANCH - NPIX
                            + (long long)gj0 * NWc + gi0;
                const long long tot = NTOTc;
                p = ((p % tot) + tot) % tot;
                int b2  = (int)(p / NANCH);
                int rem = (int)(p % NANCH);
                int a2  = rem / NPIX;
                int px2 = rem % NPIX;
                int h2 = px2 / NWc, w2 = px2 % NWc;
                const float* bo2 = out + ((size_t)(b2 * NAc + a2) * CHPA) * NPIX + px2;
                const float* gq = (const float*)&s_gq[m][0];
                float s = 0.0f;
                #pragma unroll
                for (int k = 0; k < NKc; ++k) {
                    float xv = bo2[(2*k)   * NPIX];
                    float yv = bo2[(2*k+1) * NPIX];
                    if (k == 0) { xv = sigf(xv); yv = sigf(yv); }
                    float qx = (xv + (float)w2) * SCX;
                    float qy = (yv + (float)h2) * SCY;
                    float dx = gq[2*k]   - qx;
                    float dy = gq[2*k+1] - qy;
                    float d2 = fmaf(dx, dx, dy * dy);
                    if (d2 < 6400.0f) s += __expf(2.0f - sqrtf(d2) * 0.025f) - 1.0f;
                }
                float dc = confv[j] - s * (1.0f / DENOM9);
                confLoss += 2.5f * dc * dc;
            } else if (!sil[j]) {
                confLoss += 0.5f * confv[j] * confv[j];
            }
        }
    }

    // ---- block reduction ----------------------------------------------------
    float v0 = baseLoss, v1 = confLoss;
    #pragma unroll
    for (int o = 16; o > 0; o >>= 1) {
        v0 += __shfl_down_sync(0xFFFFFFFFu, v0, o);
        v1 += __shfl_down_sync(0xFFFFFFFFu, v1, o);
    }
    if (lane == 0) s_wred[wid] = make_float2(v0, v1);
    __syncthreads();
    if (tid == 0) {
        float rb = 0.0f, rc = 0.0f;
        #pragma unroll
        for (int j = 0; j < TPB/32; ++j) { rb += s_wred[j].x; rc += s_wred[j].y; }
        g_part[blockIdx.x][0] = rb;
        g_part[blockIdx.x][1] = rc;
    }

    // ---- last-block-done final reduction ------------------------------------
    __threadfence();
    if (tid == 0) {
        int old = atomicAdd(&g_cnt, 1);
        s_last = (old == NBLK - 1);
    }
    __syncthreads();
    if (!s_last) return;

    float rb = 0.0f, rc = 0.0f;
    if (tid < NBLK) { rb = g_part[tid][0]; rc = g_part[tid][1]; }
    #pragma unroll
    for (int o = 16; o > 0; o >>= 1) {
        rb += __shfl_down_sync(0xFFFFFFFFu, rb, o);
        rc += __shfl_down_sync(0xFFFFFFFFu, rc, o);
    }
    if (lane == 0) s_wred[wid] = make_float2(rb, rc);
    __syncthreads();
    if (tid == 0) {
        float tb2 = 0.0f, tc2 = 0.0f;
        #pragma unroll
        for (int j = 0; j < TPB/32; ++j) { tb2 += s_wred[j].x; tc2 += s_wred[j].y; }
        int ev = ((const int*)epoch_ptr)[0];
        if (ev > 1000000 || ev < -1000000) ev = (int)__int_as_float(ev);
        float total = tb2;
        if (ev > 15) total += tc2;
        d_out[0] = total;
        g_cnt = 0;   // reset for graph replay
    }
}

extern "C" void kernel_launch(void* const* d_in, const int* in_sizes, int n_in,
                              void* d_out, int out_size) {
    const float* out_t = (const float*)d_in[0];
    const float* tgt   = (const float*)d_in[1];
    const float* anc   = (const float*)d_in[2];
    const void*  epoch = d_in[3];
    k_main<<<NBLK, TPB>>>(out_t, tgt, anc, epoch, (float*)d_out);
}

// round 14
// speedup vs baseline: 1.1233x; 1.1233x over previous
#include <cuda_runtime.h>
#include <math.h>

// Problem constants
#define NBc   16
#define NAc   5
#define NKc   9
#define NCc   13
#define NHc   38
#define NWc   38
#define MAXTc 50
#define NPIX  (NHc*NWc)        // 1444
#define NANCH (NAc*NPIX)       // 7220
#define NTOTc (NBc*NANCH)      // 115520
#define CHPA  (2*NKc+1+NCc)    // 32
#define TROW  21

#define TPB   256
#define BPB   ((NANCH + TPB - 1)/TPB)  // 29 blocks per batch
#define NBLK  (NBc*BPB)                // 464 blocks (<= 592 slots @4/SM: 1 wave)

#define SCX   (640.0f/38.0f)
#define SCY   (480.0f/38.0f)
#define DENOM9   57.50150489f
#define STHRESH  34.50090293f   // 0.6 * 9 * (e^2 - 1)
// ssum > STHRESH requires max corner term >= STHRESH/9 -> some d2 < 288.12
#define GATE2    290.0f

__device__ float g_part[NBLK][2];
__device__ int   g_cnt = 0;

__device__ __forceinline__ float sigf(float x) { return 1.0f / (1.0f + __expf(-x)); }

__global__ void __launch_bounds__(TPB, 4)
k_main(const float* __restrict__ out,
       const float* __restrict__ tgt,
       const float* __restrict__ anc,
       const void*  __restrict__ epoch_ptr,
       float* __restrict__ d_out) {
    __shared__ float  s_t[MAXTc*TROW];                // staged target rows
    __shared__ int    s_nv;
    __shared__ int    s_key[MAXTc];
    __shared__ float  s_cls[MAXTc];
    __shared__ __align__(16) float4 s_gq[MAXTc][5];   // corners (10 f2 slots)
    __shared__ __align__(16) float2 s_v[MAXTc*NKc];   // coord targets
    __shared__ float2 s_wred[TPB/32];
    __shared__ bool   s_last;

    const int tid  = threadIdx.x;
    const int lane = tid & 31;
    const int wid  = tid >> 5;
    const int b    = blockIdx.x / BPB;
    const int cell = (blockIdx.x % BPB) * TPB + tid;
    const bool ok  = (cell < NANCH);
    const float* tgb = tgt + (size_t)b * (MAXTc*TROW);

    // ---- per-cell channel loads, issued early; fold into Px/Py -------------
    int a = 0, h = 0, w = 0;
    const float* baseo = out;
    float Px[NKc], Py[NKc], confv = 0.0f;
    if (ok) {
        a = cell / NPIX;
        int pix = cell % NPIX;
        h = pix / NWc; w = pix % NWc;
        baseo = out + ((size_t)(b * NAc + a) * CHPA) * NPIX + pix;
        float rc = baseo[(2*NKc) * NPIX];
        #pragma unroll
        for (int k = 0; k < NKc; ++k) {
            float xv = baseo[(2*k)   * NPIX];
            float yv = baseo[(2*k+1) * NPIX];
            if (k == 0) { xv = sigf(xv); yv = sigf(yv); }
            Px[k] = (xv + (float)w) * SCX;
            Py[k] = (yv + (float)h) * SCY;
        }
        confv = sigf(rc);
    }

    // ---- stage targets coalesced -------------------------------------------
    for (int i = tid; i < MAXTc*TROW; i += TPB)
        s_t[i] = tgb[i];
    __syncthreads();

    // ---- validity prefix via ballots (warp 0) ------------------------------
    if (wid == 0) {
        unsigned m0 = __ballot_sync(0xFFFFFFFFu, s_t[lane*TROW + 1] != 0.0f);
        unsigned m1 = __ballot_sync(0xFFFFFFFFu,
                          (lane < MAXTc - 32) && (s_t[(lane+32)*TROW + 1] != 0.0f));
        if (lane == 0) {
            int nv;
            if (~m0) nv = __ffs(~m0) - 1;
            else {
                unsigned inv = (~m1) & ((1u << (MAXTc - 32)) - 1u);
                nv = inv ? 32 + __ffs(inv) - 1 : MAXTc;
            }
            s_nv = nv;
        }
    }

    // ---- per-target meta (no tconf; cheap) ---------------------------------
    if (tid < MAXTc && s_t[tid*TROW + 1] != 0.0f) {
        const int t = tid;
        const float* tb = &s_t[t*TROW];

        float gw = tb[19] * (float)NWc;
        float gh = tb[20] * (float)NHc;
        float best = -1.0f; int bn = 0;
        #pragma unroll
        for (int aa = 0; aa < NAc; ++aa) {
            float aw = anc[2*aa], ah = anc[2*aa+1];
            float cw = fminf(gw, aw), ch = fminf(gh, ah);
            float iou = 0.0f;
            if (cw > 0.0f && ch > 0.0f) {
                float ca = cw * ch;
                iou = ca / (gw * gh + aw * ah - ca);
            }
            if (iou > best) { best = iou; bn = aa; }
        }
        int gi0 = (int)floorf(tb[1] * (float)NWc);
        int gj0 = (int)floorf(tb[2] * (float)NHc);
        s_key[t] = (bn << 12) | (gj0 << 6) | gi0;
        s_cls[t] = tb[0];

        float* gq = (float*)&s_gq[t][0];
        #pragma unroll
        for (int k = 0; k < NKc; ++k) {
            float gx = tb[1 + 2*k], gy = tb[2 + 2*k];
            gq[2*k]   = gx * 640.0f;
            gq[2*k+1] = gy * 480.0f;
            s_v[t*NKc + k] = make_float2(gx * (float)NWc - (float)gi0,
                                         gy * (float)NHc - (float)gj0);
        }
        gq[18] = 1.0e9f;  gq[19] = 1.0e9f;   // sentinel 10th corner slot
    }
    __syncthreads();
    const int nv = s_nv;

    // ---- per-cell loss ------------------------------------------------------
    float baseLoss = 0.0f, confLoss = 0.0f;

    if (ok) {
        const int mykey = (a << 12) | (h << 6) | w;
        int m = -1;
        for (int t = 0; t < nv; ++t)
            if (s_key[t] == mykey) m = t;

        if (m >= 0) {
            // matched (rare): coord + CE + obj-conf (tconf computed inline)
            #pragma unroll
            for (int k = 0; k < NKc; ++k) {
                float xv = baseo[(2*k)   * NPIX];
                float yv = baseo[(2*k+1) * NPIX];
                if (k == 0) { xv = sigf(xv); yv = sigf(yv); }
                float2 v = s_v[m*NKc + k];
                float dx = xv - v.x;
                float dy = yv - v.y;
                baseLoss += 0.5f * (dx*dx + dy*dy);
            }
            float mx = -1e30f;
            #pragma unroll
            for (int c = 0; c < NCc; ++c)
                mx = fmaxf(mx, baseo[(2*NKc + 1 + c) * NPIX]);
            float se = 0.0f;
            #pragma unroll
            for (int c = 0; c < NCc; ++c)
                se += __expf(baseo[(2*NKc + 1 + c) * NPIX] - mx);
            int lab = (int)s_cls[m];
            lab = lab < 0 ? 0 : (lab > NCc - 1 ? NCc - 1 : lab);
            baseLoss += __logf(se) + mx - baseo[(2*NKc + 1 + lab) * NPIX];

            // tconf at the pidx-shifted cell for this target
            int gi0 = mykey & 63, gj0 = (mykey >> 6) & 63;
            long long p = (long long)b * NANCH - NPIX + (long long)gj0 * NWc + gi0;
            const long long tot = NTOTc;
            p = ((p % tot) + tot) % tot;
            int b2  = (int)(p / NANCH);
            int rem = (int)(p % NANCH);
            int a2  = rem / NPIX;
            int px2 = rem % NPIX;
            int h2 = px2 / NWc, w2 = px2 % NWc;
            const float* bo2 = out + ((size_t)(b2 * NAc + a2) * CHPA) * NPIX + px2;
            const float* gq = (const float*)&s_gq[m][0];
            float s = 0.0f;
            #pragma unroll
            for (int k = 0; k < NKc; ++k) {
                float xv = bo2[(2*k)   * NPIX];
                float yv = bo2[(2*k+1) * NPIX];
                if (k == 0) { xv = sigf(xv); yv = sigf(yv); }
                float qx = (xv + (float)w2) * SCX;
                float qy = (yv + (float)h2) * SCY;
                float dx = gq[2*k]   - qx;
                float dy = gq[2*k+1] - qy;
                float d2 = fmaf(dx, dx, dy * dy);
                if (d2 < 6400.0f) s += __expf(2.0f - sqrtf(d2) * 0.025f) - 1.0f;
            }
            float dc = confv - s * (1.0f / DENOM9);
            confLoss = 2.5f * dc * dc;
        } else {
            // silence check: float4 corner loads + exact-necessary gate
            bool silent = false;
            for (int t = 0; t < nv; ++t) {
                float4 q0 = s_gq[t][0];
                float4 q1 = s_gq[t][1];
                float4 q2 = s_gq[t][2];
                float4 q3 = s_gq[t][3];
                float4 q4 = s_gq[t][4];
                float d2[NKc];
                { float dx = Px[0]-q0.x, dy = Py[0]-q0.y; d2[0] = fmaf(dx,dx,dy*dy); }
                { float dx = Px[1]-q0.z, dy = Py[1]-q0.w; d2[1] = fmaf(dx,dx,dy*dy); }
                { float dx = Px[2]-q1.x, dy = Py[2]-q1.y; d2[2] = fmaf(dx,dx,dy*dy); }
                { float dx = Px[3]-q1.z, dy = Py[3]-q1.w; d2[3] = fmaf(dx,dx,dy*dy); }
                { float dx = Px[4]-q2.x, dy = Py[4]-q2.y; d2[4] = fmaf(dx,dx,dy*dy); }
                { float dx = Px[5]-q2.z, dy = Py[5]-q2.w; d2[5] = fmaf(dx,dx,dy*dy); }
                { float dx = Px[6]-q3.x, dy = Py[6]-q3.y; d2[6] = fmaf(dx,dx,dy*dy); }
                { float dx = Px[7]-q3.z, dy = Py[7]-q3.w; d2[7] = fmaf(dx,dx,dy*dy); }
                { float dx = Px[8]-q4.x, dy = Py[8]-q4.y; d2[8] = fmaf(dx,dx,dy*dy); }
                float m01 = fminf(d2[0], d2[1]), m23 = fminf(d2[2], d2[3]);
                float m45 = fminf(d2[4], d2[5]), m67 = fminf(d2[6], d2[7]);
                float dmin = fminf(fminf(fminf(m01, m23), fminf(m45, m67)), d2[8]);
                if (dmin < GATE2) {            // rare (~2-3% of pairs)
                    float ssum = 0.0f;
                    #pragma unroll
                    for (int k = 0; k < NKc; ++k)
                        if (d2[k] < 6400.0f)
                            ssum += __expf(2.0f - sqrtf(d2[k]) * 0.025f) - 1.0f;
                    if (ssum > STHRESH) { silent = true; break; }
                }
            }
            if (!silent) confLoss = 0.5f * confv * confv;
        }
    }

    // ---- block reduction ----------------------------------------------------
    float v0 = baseLoss, v1 = confLoss;
    #pragma unroll
    for (int o = 16; o > 0; o >>= 1) {
        v0 += __shfl_down_sync(0xFFFFFFFFu, v0, o);
        v1 += __shfl_down_sync(0xFFFFFFFFu, v1, o);
    }
    if (lane == 0) s_wred[wid] = make_float2(v0, v1);
    __syncthreads();
    if (tid == 0) {
        float rb = 0.0f, rc = 0.0f;
        #pragma unroll
        for (int j = 0; j < TPB/32; ++j) { rb += s_wred[j].x; rc += s_wred[j].y; }
        g_part[blockIdx.x][0] = rb;
        g_part[blockIdx.x][1] = rc;
    }

    // ---- last-block-done final reduction ------------------------------------
    __threadfence();
    if (tid == 0) {
        int old = atomicAdd(&g_cnt, 1);
        s_last = (old == NBLK - 1);
    }
    __syncthreads();
    if (!s_last) return;

    float rb = 0.0f, rc = 0.0f;
    for (int idx = tid; idx < NBLK; idx += TPB) {
        rb += g_part[idx][0];
        rc += g_part[idx][1];
    }
    #pragma unroll
    for (int o = 16; o > 0; o >>= 1) {
        rb += __shfl_down_sync(0xFFFFFFFFu, rb, o);
        rc += __shfl_down_sync(0xFFFFFFFFu, rc, o);
    }
    if (lane == 0) s_wred[wid] = make_float2(rb, rc);
    __syncthreads();
    if (tid == 0) {
        float tb2 = 0.0f, tc2 = 0.0f;
        #pragma unroll
        for (int j = 0; j < TPB/32; ++j) { tb2 += s_wred[j].x; tc2 += s_wred[j].y; }
        int ev = ((const int*)epoch_ptr)[0];
        if (ev > 1000000 || ev < -1000000) ev = (int)__int_as_float(ev);
        float total = tb2;
        if (ev > 15) total += tc2;
        d_out[0] = total;
        g_cnt = 0;   // reset for graph replay
    }
}

extern "C" void kernel_launch(void* const* d_in, const int* in_sizes, int n_in,
                              void* d_out, int out_size) {
    const float* out_t = (const float*)d_in[0];
    const float* tgt   = (const float*)d_in[1];
    const float* anc   = (const float*)d_in[2];
    const void*  epoch = d_in[3];
    k_main<<<NBLK, TPB>>>(out_t, tgt, anc, epoch, (float*)d_out);
}